// round 1
// baseline (speedup 1.0000x reference)
#include <cuda_runtime.h>
#include <cuda_bf16.h>

// Accumulators per (scale, image): C, S, inter(=sum p*t), z(=sum p*p), psum(=sum p)
#define BN 32
#define NACC 5
__device__ float g_acc[3 * BN * NACC];

__global__ void zero_acc_kernel() {
    int i = threadIdx.x;
    if (i < 3 * BN * NACC) g_acc[i] = 0.0f;
}

__device__ __forceinline__ float warp_sum(float v) {
    #pragma unroll
    for (int o = 16; o > 0; o >>= 1) v += __shfl_down_sync(0xffffffffu, v, o);
    return v;
}

// One scale. H,W = logits spatial dims; ST = 512/H (nearest-ds stride into full targets).
// grid: (blocksPerImage, BN). Each block grid-strides over pixels of one image.
template<int H, int W, int ST>
__global__ void scale_kernel(const float* __restrict__ logits,
                             const int*   __restrict__ targets,
                             int scale_idx) {
    const int img = blockIdx.y;
    const float* __restrict__ lg = logits + (size_t)img * H * W;
    const int*   __restrict__ tg = targets + (size_t)img * 512 * 512;

    float c = 0.f, s = 0.f, inter = 0.f, z = 0.f, ps = 0.f;

    const int npix   = H * W;
    const int stride = gridDim.x * blockDim.x;
    for (int idx = blockIdx.x * blockDim.x + threadIdx.x; idx < npix; idx += stride) {
        const int i = idx >> 9 >> (9 - __popc(0)) ? 0 : idx / W;   // (kept simple below)
        const int ii = idx / W;
        const int jj = idx - ii * W;
        const int bi = ii * ST;
        const int bj = jj * ST;
        const int* __restrict__ row = tg + bi * 512;

        const int t = row[bj];
        const float x = lg[idx];
        const float p = 1.0f / (1.0f + __expf(-x));
        ps += p;
        z  += p * p;
        if (t) {
            s     += 1.0f;
            inter += p;
            int sum = 1;  // center (binary targets)
            sum += (ii > 0)     ? row[bj - ST * 512] : 0;
            sum += (ii < H - 1) ? row[bj + ST * 512] : 0;
            sum += (jj > 0)     ? row[bj - ST]       : 0;
            sum += (jj < W - 1) ? row[bj + ST]       : 0;
            if (sum != 5) c += 1.0f;  // boundary fg pixel
        }
    }

    // warp-level reduce, then per-warp-leader atomics (few hundred per address total)
    c     = warp_sum(c);
    s     = warp_sum(s);
    inter = warp_sum(inter);
    z     = warp_sum(z);
    ps    = warp_sum(ps);
    if ((threadIdx.x & 31) == 0) {
        float* a = &g_acc[(scale_idx * BN + img) * NACC];
        atomicAdd(&a[0], c);
        atomicAdd(&a[1], s);
        atomicAdd(&a[2], inter);
        atomicAdd(&a[3], z);
        atomicAdd(&a[4], ps);
    }
}

__global__ void final_kernel(const float* __restrict__ valid_mask, float* __restrict__ out) {
    if (threadIdx.x != 0 || blockIdx.x != 0) return;
    const float SMOOTH = 1e-5f;
    const float ws[3] = { 1.0f / 1.75f, 0.5f / 1.75f, 0.25f / 1.75f };
    const float inv_hw[3] = { 1.0f / (512.f * 512.f), 1.0f / (256.f * 256.f), 1.0f / (128.f * 128.f) };

    float vm[BN];
    float cnt = 0.f;
    #pragma unroll
    for (int i = 0; i < BN; i++) {
        vm[i] = (valid_mask[i] >= 0.5f) ? 1.0f : 0.0f;
        cnt += vm[i];
    }

    float loss = 0.f;
    for (int sc = 0; sc < 3; sc++) {
        float acc = 0.f;
        for (int im = 0; im < BN; im++) {
            const float* a = &g_acc[(sc * BN + im) * NACC];
            const float C = a[0], S = a[1], I = a[2], Z = a[3], P = a[4];
            float alpha = 2.0f * (1.0f - (C + SMOOTH) / (S + SMOOTH)) - 1.0f;
            alpha = fminf(alpha, 0.8f);
            const float num = Z + S - 2.0f * I + SMOOTH;
            const float den = Z + S - (1.0f + alpha) * I + SMOOTH;
            const float dou = num / den;
            const float per = (S > 0.f) ? dou : P * inv_hw[sc];
            acc += per * vm[im];
        }
        loss += ws[sc] * ((cnt > 0.f) ? (acc / cnt) : 0.0f);
    }
    out[0] = loss;
}

extern "C" void kernel_launch(void* const* d_in, const int* in_sizes, int n_in,
                              void* d_out, int out_size) {
    const float* l0 = (const float*)d_in[0];   // [8,4,512,512]
    const float* l1 = (const float*)d_in[1];   // [8,4,256,256]
    const float* l2 = (const float*)d_in[2];   // [8,4,128,128]
    const int*   tg = (const int*)d_in[3];     // [8,4,512,512]
    const float* vm = (const float*)d_in[4];   // [8,4]
    float* out = (float*)d_out;

    zero_acc_kernel<<<1, 512>>>();
    scale_kernel<512, 512, 1><<<dim3(64, BN), 256>>>(l0, tg, 0);
    scale_kernel<256, 256, 2><<<dim3(16, BN), 256>>>(l1, tg, 1);
    scale_kernel<128, 128, 4><<<dim3(4,  BN), 256>>>(l2, tg, 2);
    final_kernel<<<1, 32>>>(vm, out);
}

// round 2
// speedup vs baseline: 2.3504x; 2.3504x over previous
#include <cuda_runtime.h>
#include <cuda_bf16.h>

// Accumulators per (scale, image): C, S, inter, z(=sum p^2), psum
#define BN 32
#define NACC 5
__device__ float g_acc[3 * BN * NACC];

__global__ void zero_acc_kernel() {
    int i = threadIdx.x;
    if (i < 3 * BN * NACC) g_acc[i] = 0.0f;
}

__device__ __forceinline__ float warp_sum(float v) {
    #pragma unroll
    for (int o = 16; o > 0; o >>= 1) v += __shfl_down_sync(0xffffffffu, v, o);
    return v;
}

__device__ __forceinline__ float fsigmoid(float x) {
    return __fdividef(1.0f, 1.0f + __expf(-x));
}

struct Acc { float c, s, inter, z, ps; };

__device__ __forceinline__ void commit(int scale_idx, int img, Acc& a) {
    a.c     = warp_sum(a.c);
    a.s     = warp_sum(a.s);
    a.inter = warp_sum(a.inter);
    a.z     = warp_sum(a.z);
    a.ps    = warp_sum(a.ps);
    if ((threadIdx.x & 31) == 0) {
        float* g = &g_acc[(scale_idx * BN + img) * NACC];
        atomicAdd(&g[0], a.c);
        atomicAdd(&g[1], a.s);
        atomicAdd(&g[2], a.inter);
        atomicAdd(&g[3], a.z);
        atomicAdd(&g[4], a.ps);
    }
}

// ---- scale 0: H=W=512, stride 1, vectorized by 4 ----
__device__ void do_scale0(const float* __restrict__ logits,
                          const int*   __restrict__ targets,
                          int img, int blk, int bpi) {
    const float* __restrict__ lg = logits  + (size_t)img * 512 * 512;
    const int*   __restrict__ tg = targets + (size_t)img * 512 * 512;

    Acc a = {0.f, 0.f, 0.f, 0.f, 0.f};

    const int nvec    = 512 * 512 / 4;                 // 65536
    const int threads = bpi * blockDim.x;              // threads per image
    for (int v = blk * blockDim.x + threadIdx.x; v < nvec; v += threads) {
        const int p  = v << 2;
        const int ii = p >> 9;
        const int jj = p & 511;

        const float4 xl = *reinterpret_cast<const float4*>(lg + p);
        const int4   tc = *reinterpret_cast<const int4*>(tg + p);

        float px[4] = { fsigmoid(xl.x), fsigmoid(xl.y), fsigmoid(xl.z), fsigmoid(xl.w) };
        int   tcs[4] = { tc.x, tc.y, tc.z, tc.w };
        a.ps += px[0] + px[1] + px[2] + px[3];
        a.z  += px[0]*px[0] + px[1]*px[1] + px[2]*px[2] + px[3]*px[3];

        const int any_fg = tc.x | tc.y | tc.z | tc.w;
        if (any_fg) {
            int4 tu = make_int4(0,0,0,0), td = make_int4(0,0,0,0);
            if (ii > 0)   tu = *reinterpret_cast<const int4*>(tg + p - 512);
            if (ii < 511) td = *reinterpret_cast<const int4*>(tg + p + 512);
            const int tl = (jj > 0)   ? tg[p - 1] : 0;
            const int tr = (jj < 508) ? tg[p + 4] : 0;

            int tus[4] = { tu.x, tu.y, tu.z, tu.w };
            int tds[4] = { td.x, td.y, td.z, td.w };
            int lf[4]  = { tl, tc.x, tc.y, tc.z };
            int rt[4]  = { tc.y, tc.z, tc.w, tr };
            #pragma unroll
            for (int l = 0; l < 4; l++) {
                if (tcs[l]) {
                    a.s     += 1.0f;
                    a.inter += px[l];
                    const int sum = 1 + tus[l] + tds[l] + lf[l] + rt[l];
                    if (sum != 5) a.c += 1.0f;
                }
            }
        }
    }
    commit(0, img, a);
}

// ---- scales 1/2: H=W, target stride ST into 512x512 ----
template<int H, int ST>
__device__ void do_scale_ds(const float* __restrict__ logits,
                            const int*   __restrict__ targets,
                            int img, int blk, int bpi, int scale_idx) {
    const float* __restrict__ lg = logits  + (size_t)img * H * H;
    const int*   __restrict__ tg = targets + (size_t)img * 512 * 512;

    Acc a = {0.f, 0.f, 0.f, 0.f, 0.f};

    const int npix    = H * H;
    const int threads = bpi * blockDim.x;
    for (int p = blk * blockDim.x + threadIdx.x; p < npix; p += threads) {
        const int ii = p / H;
        const int jj = p - ii * H;
        const int b  = (ii * ST) * 512 + jj * ST;

        const int   t = tg[b];
        const float pr = fsigmoid(lg[p]);
        a.ps += pr;
        a.z  += pr * pr;
        if (t) {
            a.s     += 1.0f;
            a.inter += pr;
            int sum = 1;
            sum += (ii > 0)     ? tg[b - ST * 512] : 0;
            sum += (ii < H - 1) ? tg[b + ST * 512] : 0;
            sum += (jj > 0)     ? tg[b - ST]       : 0;
            sum += (jj < H - 1) ? tg[b + ST]       : 0;
            if (sum != 5) a.c += 1.0f;
        }
    }
    commit(scale_idx, img, a);
}

// Block partition: [0,B2) scale2, [B2,B2+B1) scale1, rest scale0.
#define BPI2 4
#define BPI1 8
#define BPI0 32
#define B2 (BN * BPI2)   // 128
#define B1 (BN * BPI1)   // 256
#define B0 (BN * BPI0)   // 1024

__global__ void __launch_bounds__(256)
fused_kernel(const float* __restrict__ l0,
             const float* __restrict__ l1,
             const float* __restrict__ l2,
             const int*   __restrict__ tg) {
    const int bid = blockIdx.x;
    if (bid < B2) {
        const int img = bid / BPI2, blk = bid % BPI2;
        do_scale_ds<128, 4>(l2, tg, img, blk, BPI2, 2);
    } else if (bid < B2 + B1) {
        const int b = bid - B2;
        const int img = b / BPI1, blk = b % BPI1;
        do_scale_ds<256, 2>(l1, tg, img, blk, BPI1, 1);
    } else {
        const int b = bid - B2 - B1;
        const int img = b / BPI0, blk = b % BPI0;
        do_scale0(l0, tg, img, blk, BPI0);
    }
}

__global__ void final_kernel(const float* __restrict__ valid_mask, float* __restrict__ out) {
    const float SMOOTH = 1e-5f;
    const float ws[3] = { 1.0f / 1.75f, 0.5f / 1.75f, 0.25f / 1.75f };
    const float inv_hw[3] = { 1.0f / (512.f * 512.f), 1.0f / (256.f * 256.f), 1.0f / (128.f * 128.f) };

    const int im = threadIdx.x;  // 32 lanes, one per image
    const float v = (valid_mask[im] >= 0.5f) ? 1.0f : 0.0f;
    const float cnt = warp_sum(v);
    float contrib = 0.f;
    #pragma unroll
    for (int sc = 0; sc < 3; sc++) {
        const float* a = &g_acc[(sc * BN + im) * NACC];
        const float C = a[0], S = a[1], I = a[2], Z = a[3], P = a[4];
        float alpha = 2.0f * (1.0f - (C + SMOOTH) / (S + SMOOTH)) - 1.0f;
        alpha = fminf(alpha, 0.8f);
        const float num = Z + S - 2.0f * I + SMOOTH;
        const float den = Z + S - (1.0f + alpha) * I + SMOOTH;
        const float dou = num / den;
        const float per = (S > 0.f) ? dou : P * inv_hw[sc];
        contrib += ws[sc] * per * v;
    }
    contrib = warp_sum(contrib);
    if (threadIdx.x == 0) out[0] = (cnt > 0.f) ? (contrib / cnt) : 0.0f;
}

extern "C" void kernel_launch(void* const* d_in, const int* in_sizes, int n_in,
                              void* d_out, int out_size) {
    const float* l0 = (const float*)d_in[0];   // [8,4,512,512]
    const float* l1 = (const float*)d_in[1];   // [8,4,256,256]
    const float* l2 = (const float*)d_in[2];   // [8,4,128,128]
    const int*   tg = (const int*)d_in[3];     // [8,4,512,512]
    const float* vm = (const float*)d_in[4];   // [8,4]
    float* out = (float*)d_out;

    zero_acc_kernel<<<1, 512>>>();
    fused_kernel<<<B0 + B1 + B2, 256>>>(l0, l1, l2, tg);
    final_kernel<<<1, 32>>>(vm, out);
}

// round 3
// speedup vs baseline: 3.0058x; 1.2788x over previous
#include <cuda_runtime.h>
#include <cuda_bf16.h>

#define BN 32
#define BPI2 8
#define BPI1 16
#define BPI0 32
#define NB2 (BN * BPI2)            // 256
#define NB1 (BN * BPI1)            // 512
#define NB0 (BN * BPI0)            // 1024
#define NBLK (NB2 + NB1 + NB0)     // 1792

// Per-block partials: [NBLK][5] = {C, S, inter, z, psum}. Overwritten every call.
__device__ float g_part[NBLK * 5];
__device__ unsigned g_count = 0;   // last-block counter; reset to 0 by last block each call

__device__ __forceinline__ float warp_sum(float v) {
    #pragma unroll
    for (int o = 16; o > 0; o >>= 1) v += __shfl_down_sync(0xffffffffu, v, o);
    return v;
}

__device__ __forceinline__ float fsigmoid(float x) {
    return __fdividef(1.0f, 1.0f + __expf(-x));
}

struct Acc { float c, s, inter, z, ps; };

// Block-level reduce of 5 accumulators, thread 0 writes the block's partial slot.
__device__ __forceinline__ void commit(Acc& a, int slot, float* s_red) {
    a.c     = warp_sum(a.c);
    a.s     = warp_sum(a.s);
    a.inter = warp_sum(a.inter);
    a.z     = warp_sum(a.z);
    a.ps    = warp_sum(a.ps);
    const int wid = threadIdx.x >> 5;
    if ((threadIdx.x & 31) == 0) {
        float* r = s_red + wid * 5;
        r[0] = a.c; r[1] = a.s; r[2] = a.inter; r[3] = a.z; r[4] = a.ps;
    }
    __syncthreads();
    if (threadIdx.x == 0) {
        float o[5] = {0.f, 0.f, 0.f, 0.f, 0.f};
        const int nw = blockDim.x >> 5;
        for (int w = 0; w < nw; w++)
            #pragma unroll
            for (int k = 0; k < 5; k++) o[k] += s_red[w * 5 + k];
        float* g = &g_part[slot * 5];
        #pragma unroll
        for (int k = 0; k < 5; k++) g[k] = o[k];
    }
}

// ---- scale 0: 512x512, stride 1, vectorized by 4 ----
__device__ Acc do_scale0(const float* __restrict__ logits,
                         const int*   __restrict__ targets,
                         int img, int blk) {
    const float* __restrict__ lg = logits  + (size_t)img * 512 * 512;
    const int*   __restrict__ tg = targets + (size_t)img * 512 * 512;

    Acc a = {0.f, 0.f, 0.f, 0.f, 0.f};
    const int nvec    = 512 * 512 / 4;
    const int threads = BPI0 * blockDim.x;
    for (int v = blk * blockDim.x + threadIdx.x; v < nvec; v += threads) {
        const int p  = v << 2;
        const int ii = p >> 9;
        const int jj = p & 511;

        const float4 xl = *reinterpret_cast<const float4*>(lg + p);
        const int4   tc = *reinterpret_cast<const int4*>(tg + p);

        float px[4] = { fsigmoid(xl.x), fsigmoid(xl.y), fsigmoid(xl.z), fsigmoid(xl.w) };
        int  tcs[4] = { tc.x, tc.y, tc.z, tc.w };
        a.ps += px[0] + px[1] + px[2] + px[3];
        a.z  += px[0]*px[0] + px[1]*px[1] + px[2]*px[2] + px[3]*px[3];

        if (tc.x | tc.y | tc.z | tc.w) {
            int4 tu = make_int4(0,0,0,0), td = make_int4(0,0,0,0);
            if (ii > 0)   tu = *reinterpret_cast<const int4*>(tg + p - 512);
            if (ii < 511) td = *reinterpret_cast<const int4*>(tg + p + 512);
            const int tl = (jj > 0)   ? tg[p - 1] : 0;
            const int tr = (jj < 508) ? tg[p + 4] : 0;

            int tus[4] = { tu.x, tu.y, tu.z, tu.w };
            int tds[4] = { td.x, td.y, td.z, td.w };
            int lf[4]  = { tl, tc.x, tc.y, tc.z };
            int rt[4]  = { tc.y, tc.z, tc.w, tr };
            #pragma unroll
            for (int l = 0; l < 4; l++) {
                if (tcs[l]) {
                    a.s     += 1.0f;
                    a.inter += px[l];
                    if (1 + tus[l] + tds[l] + lf[l] + rt[l] != 5) a.c += 1.0f;
                }
            }
        }
    }
    return a;
}

// ---- scales 1/2: H=W, target stride ST into 512x512 ----
template<int H, int ST, int BPI>
__device__ Acc do_scale_ds(const float* __restrict__ logits,
                           const int*   __restrict__ targets,
                           int img, int blk) {
    const float* __restrict__ lg = logits  + (size_t)img * H * H;
    const int*   __restrict__ tg = targets + (size_t)img * 512 * 512;

    Acc a = {0.f, 0.f, 0.f, 0.f, 0.f};
    const int npix    = H * H;
    const int threads = BPI * blockDim.x;
    for (int p = blk * blockDim.x + threadIdx.x; p < npix; p += threads) {
        const int ii = p / H;
        const int jj = p - ii * H;
        const int b  = (ii * ST) * 512 + jj * ST;

        const int   t  = tg[b];
        const float pr = fsigmoid(lg[p]);
        a.ps += pr;
        a.z  += pr * pr;
        if (t) {
            a.s     += 1.0f;
            a.inter += pr;
            int sum = 1;
            sum += (ii > 0)     ? tg[b - ST * 512] : 0;
            sum += (ii < H - 1) ? tg[b + ST * 512] : 0;
            sum += (jj > 0)     ? tg[b - ST]       : 0;
            sum += (jj < H - 1) ? tg[b + ST]       : 0;
            if (sum != 5) a.c += 1.0f;
        }
    }
    return a;
}

__global__ void __launch_bounds__(256)
fused_kernel(const float* __restrict__ l0,
             const float* __restrict__ l1,
             const float* __restrict__ l2,
             const int*   __restrict__ tg,
             const float* __restrict__ vm,
             float* __restrict__ out) {
    __shared__ float s_red[8 * 5];
    __shared__ bool  s_last;
    __shared__ float s_contrib[96];
    __shared__ float s_valid[BN];

    const int bid = blockIdx.x;
    Acc a;
    if (bid < NB2) {
        a = do_scale_ds<128, 4, BPI2>(l2, tg, bid / BPI2, bid % BPI2);
    } else if (bid < NB2 + NB1) {
        const int b = bid - NB2;
        a = do_scale_ds<256, 2, BPI1>(l1, tg, b / BPI1, b % BPI1);
    } else {
        const int b = bid - NB2 - NB1;
        a = do_scale0(l0, tg, b / BPI0, b % BPI0);
    }
    commit(a, bid, s_red);

    // last-block final reduction
    __syncthreads();
    if (threadIdx.x == 0) {
        __threadfence();
        unsigned r = atomicAdd(&g_count, 1u);
        s_last = (r == NBLK - 1);
    }
    __syncthreads();
    if (!s_last) return;

    const int tid = threadIdx.x;
    if (tid == 0) g_count = 0;           // reset for next graph replay
    if (tid < BN) s_valid[tid] = (vm[tid] >= 0.5f) ? 1.0f : 0.0f;
    __syncthreads();

    if (tid < 96) {
        const int sc  = tid >> 5;        // 0,1,2  (here sc index 0 = scale2 layout order below)
        const int img = tid & 31;
        // slot ranges: scale2 [0,NB2), scale1 [NB2,NB2+NB1), scale0 [NB2+NB1,NBLK)
        int base, cntb;
        if      (sc == 0) { base = (NB2 + NB1) + img * BPI0; cntb = BPI0; }  // scale0
        else if (sc == 1) { base = NB2 + img * BPI1;         cntb = BPI1; }  // scale1
        else              { base = img * BPI2;               cntb = BPI2; }  // scale2

        float C = 0.f, S = 0.f, I = 0.f, Z = 0.f, P = 0.f;
        for (int b = 0; b < cntb; b++) {
            const float* g = &g_part[(base + b) * 5];
            C += g[0]; S += g[1]; I += g[2]; Z += g[3]; P += g[4];
        }
        const float SMOOTH = 1e-5f;
        const float ws[3]     = { 1.0f / 1.75f, 0.5f / 1.75f, 0.25f / 1.75f };
        const float inv_hw[3] = { 1.0f / (512.f * 512.f), 1.0f / (256.f * 256.f), 1.0f / (128.f * 128.f) };
        float alpha = 2.0f * (1.0f - (C + SMOOTH) / (S + SMOOTH)) - 1.0f;
        alpha = fminf(alpha, 0.8f);
        const float num = Z + S - 2.0f * I + SMOOTH;
        const float den = Z + S - (1.0f + alpha) * I + SMOOTH;
        const float dou = num / den;
        const float per = (S > 0.f) ? dou : P * inv_hw[sc];
        s_contrib[tid] = ws[sc] * per * s_valid[img];
    }
    __syncthreads();
    if (tid == 0) {
        float sum = 0.f, cnt = 0.f;
        #pragma unroll
        for (int i = 0; i < 96; i++) sum += s_contrib[i];
        #pragma unroll
        for (int i = 0; i < BN; i++) cnt += s_valid[i];
        out[0] = (cnt > 0.f) ? (sum / cnt) : 0.0f;
    }
}

extern "C" void kernel_launch(void* const* d_in, const int* in_sizes, int n_in,
                              void* d_out, int out_size) {
    const float* l0 = (const float*)d_in[0];   // [8,4,512,512]
    const float* l1 = (const float*)d_in[1];   // [8,4,256,256]
    const float* l2 = (const float*)d_in[2];   // [8,4,128,128]
    const int*   tg = (const int*)d_in[3];     // [8,4,512,512]
    const float* vm = (const float*)d_in[4];   // [8,4]
    float* out = (float*)d_out;

    fused_kernel<<<NBLK, 256>>>(l0, l1, l2, tg, vm, out);
}